// round 1
// baseline (speedup 1.0000x reference)
#include <cuda_runtime.h>
#include <cstdint>

// ---------------------------------------------------------------------------
// EnhancedLocalAttentionWithGQA: TF32 tensor-core implementation (round 1)
//
// Shapes: B=2, L=4096, C=2048, H=16, D=128, G=2 (g = h % 2), W=256, stride 128
// Only windows n=0..15 contribute to the output (reshape truncation).
// Pipeline:
//   1) Q = x@Wq+bq            [8192 x 2048]   (tf32 mma GEMM)
//   2) K = x@Wk+bk            [8192 x 256]
//   3) V = x@Wv+bv            [8192 x 256]
//   4) S = (Qw @ Kw^T)*scale  512 batches of [256 x 256], K=128
//   5) softmax rows of S
//   6) O = P @ Vw             512 batches of [256 x 128], K=256
//   7) out = O@Wo+bo          [8192 x 2048]
// ---------------------------------------------------------------------------

#define DEV_INLINE __device__ __forceinline__

constexpr int BM = 128, BN = 128, BK = 32;
constexpr int WM = 64,  WN = 32;           // 2 x 4 warp grid, 8 warps
constexpr int APAD = 4, BPAD = 4;

// Scratch (device globals: allocation-free)
__device__ float g_Q[2u * 4096 * 2048];    // 67 MB  [B, L, H*D]
__device__ float g_K[2u * 4096 * 256];     // 8.4 MB [B, L, G*D]
__device__ float g_V[2u * 4096 * 256];     // 8.4 MB
__device__ float g_S[512u * 256 * 256];    // 134 MB [(b*16+h)*16+n, 256, 256]
__device__ float g_O[2u * 4096 * 2048];    // 67 MB  [B, t, H*D]

DEV_INLINE uint32_t f2tf(float f) {
    uint32_t u;
    asm("cvt.rna.tf32.f32 %0, %1;" : "=r"(u) : "f"(f));
    return u;
}

DEV_INLINE void mma_tf32(float c[4],
                         uint32_t a0, uint32_t a1, uint32_t a2, uint32_t a3,
                         uint32_t b0, uint32_t b1) {
    asm volatile(
        "mma.sync.aligned.m16n8k8.row.col.f32.tf32.tf32.f32 "
        "{%0,%1,%2,%3}, {%4,%5,%6,%7}, {%8,%9}, {%0,%1,%2,%3};\n"
        : "+f"(c[0]), "+f"(c[1]), "+f"(c[2]), "+f"(c[3])
        : "r"(a0), "r"(a1), "r"(a2), "r"(a3), "r"(b0), "r"(b1));
}

// Generic batched TF32 GEMM: C = alpha * A @ op(B) + bias
//   BTRANS=false: B is [K][N] row-major (ldb over k rows)  -> smem Bs[k][n]
//   BTRANS=true : B is [N][K] row-major (ldb over n rows)  -> smem Bs[n][k]
// Batch z -> (b, h, n) with base = b*sb + h*sh + n*sn per matrix;
// B uses group index (h % hmodB) instead of h.
template <bool BTRANS>
__global__ __launch_bounds__(256) void gemm_tf32(
    const float* __restrict__ A, const float* __restrict__ B,
    const float* __restrict__ bias, float* __restrict__ C,
    int K, int lda, int ldb, int ldc,
    long A_sb, long A_sh, long A_sn,
    long B_sb, long B_sh, long B_sn, int hmodB,
    long C_sb, long C_sh, long C_sn,
    int NH, int NW, float alpha)
{
    __shared__ uint32_t As[BM * (BK + APAD)];
    __shared__ uint32_t Bs[BTRANS ? (BN * (BK + BPAD)) : (BK * (BN + BPAD))];

    const int z = blockIdx.z;
    const int b = z / (NH * NW);
    const int h = (z / NW) % NH;
    const int nw = z % NW;
    A += (size_t)b * A_sb + (size_t)h * A_sh + (size_t)nw * A_sn;
    B += (size_t)b * B_sb + (size_t)(h % hmodB) * B_sh + (size_t)nw * B_sn;
    C += (size_t)b * C_sb + (size_t)h * C_sh + (size_t)nw * C_sn;

    const int n0 = blockIdx.x * BN;
    const int m0 = blockIdx.y * BM;
    const int tid = threadIdx.x;
    const int w = tid >> 5;
    const int lane = tid & 31;
    const int g = lane >> 2;
    const int tg = lane & 3;
    const int wm = (w & 1) * WM;
    const int wn = (w >> 1) * WN;

    float acc[4][4][4];
#pragma unroll
    for (int mi = 0; mi < 4; mi++)
#pragma unroll
        for (int ni = 0; ni < 4; ni++)
#pragma unroll
            for (int r = 0; r < 4; r++) acc[mi][ni][r] = 0.0f;

    for (int k0 = 0; k0 < K; k0 += BK) {
        // ---- load A tile (BM x BK), convert to tf32 ----
        {
            const int r0 = tid >> 3;             // 0..31
            const int c4 = (tid & 7) * 4;        // 0..28
#pragma unroll
            for (int i = 0; i < 4; i++) {
                const int row = r0 + i * 32;
                const float4 v = *reinterpret_cast<const float4*>(
                    A + (size_t)(m0 + row) * lda + k0 + c4);
                uint4 u = make_uint4(f2tf(v.x), f2tf(v.y), f2tf(v.z), f2tf(v.w));
                *reinterpret_cast<uint4*>(&As[row * (BK + APAD) + c4]) = u;
            }
        }
        // ---- load B tile ----
        if (BTRANS) {
            const int r0 = tid >> 3;             // n index 0..31
            const int c4 = (tid & 7) * 4;        // k offset
#pragma unroll
            for (int i = 0; i < 4; i++) {
                const int row = r0 + i * 32;
                const float4 v = *reinterpret_cast<const float4*>(
                    B + (size_t)(n0 + row) * ldb + k0 + c4);
                uint4 u = make_uint4(f2tf(v.x), f2tf(v.y), f2tf(v.z), f2tf(v.w));
                *reinterpret_cast<uint4*>(&Bs[row * (BK + BPAD) + c4]) = u;
            }
        } else {
            const int r0 = tid >> 5;             // k index 0..7
            const int c4 = (tid & 31) * 4;       // n offset 0..124
#pragma unroll
            for (int i = 0; i < 4; i++) {
                const int krow = r0 + i * 8;
                const float4 v = *reinterpret_cast<const float4*>(
                    B + (size_t)(k0 + krow) * ldb + n0 + c4);
                uint4 u = make_uint4(f2tf(v.x), f2tf(v.y), f2tf(v.z), f2tf(v.w));
                *reinterpret_cast<uint4*>(&Bs[krow * (BN + BPAD) + c4]) = u;
            }
        }
        __syncthreads();

        // ---- compute: 4 k8 steps ----
#pragma unroll
        for (int kk = 0; kk < BK / 8; kk++) {
            const int ks = kk * 8;
            uint32_t af[4][4], bf[4][2];
#pragma unroll
            for (int mi = 0; mi < 4; mi++) {
                const int mb = wm + mi * 16;
                af[mi][0] = As[(mb + g) * (BK + APAD) + ks + tg];
                af[mi][1] = As[(mb + g + 8) * (BK + APAD) + ks + tg];
                af[mi][2] = As[(mb + g) * (BK + APAD) + ks + tg + 4];
                af[mi][3] = As[(mb + g + 8) * (BK + APAD) + ks + tg + 4];
            }
#pragma unroll
            for (int ni = 0; ni < 4; ni++) {
                const int nb = wn + ni * 8;
                if (BTRANS) {
                    bf[ni][0] = Bs[(nb + g) * (BK + BPAD) + ks + tg];
                    bf[ni][1] = Bs[(nb + g) * (BK + BPAD) + ks + tg + 4];
                } else {
                    bf[ni][0] = Bs[(ks + tg) * (BN + BPAD) + nb + g];
                    bf[ni][1] = Bs[(ks + tg + 4) * (BN + BPAD) + nb + g];
                }
            }
#pragma unroll
            for (int mi = 0; mi < 4; mi++)
#pragma unroll
                for (int ni = 0; ni < 4; ni++)
                    mma_tf32(acc[mi][ni], af[mi][0], af[mi][1], af[mi][2],
                             af[mi][3], bf[ni][0], bf[ni][1]);
        }
        __syncthreads();
    }

    // ---- epilogue ----
#pragma unroll
    for (int mi = 0; mi < 4; mi++) {
        const int r0 = m0 + wm + mi * 16 + g;
#pragma unroll
        for (int ni = 0; ni < 4; ni++) {
            const int col = n0 + wn + ni * 8 + 2 * tg;
            float bz0 = 0.0f, bz1 = 0.0f;
            if (bias) { bz0 = bias[col]; bz1 = bias[col + 1]; }
            float2 v0 = make_float2(acc[mi][ni][0] * alpha + bz0,
                                    acc[mi][ni][1] * alpha + bz1);
            float2 v1 = make_float2(acc[mi][ni][2] * alpha + bz0,
                                    acc[mi][ni][3] * alpha + bz1);
            *reinterpret_cast<float2*>(C + (size_t)r0 * ldc + col) = v0;
            *reinterpret_cast<float2*>(C + (size_t)(r0 + 8) * ldc + col) = v1;
        }
    }
}

// Row softmax over rows of 256 floats; one warp per row.
__global__ __launch_bounds__(256) void softmax_rows(float* __restrict__ S) {
    const int row = blockIdx.x * 8 + (threadIdx.x >> 5);
    const int l = threadIdx.x & 31;
    float* p = S + (size_t)row * 256;

    float4 v0 = *reinterpret_cast<const float4*>(p + l * 4);
    float4 v1 = *reinterpret_cast<const float4*>(p + 128 + l * 4);

    float mx = fmaxf(fmaxf(fmaxf(v0.x, v0.y), fmaxf(v0.z, v0.w)),
                     fmaxf(fmaxf(v1.x, v1.y), fmaxf(v1.z, v1.w)));
#pragma unroll
    for (int off = 16; off; off >>= 1)
        mx = fmaxf(mx, __shfl_xor_sync(0xFFFFFFFFu, mx, off));

    v0.x = __expf(v0.x - mx); v0.y = __expf(v0.y - mx);
    v0.z = __expf(v0.z - mx); v0.w = __expf(v0.w - mx);
    v1.x = __expf(v1.x - mx); v1.y = __expf(v1.y - mx);
    v1.z = __expf(v1.z - mx); v1.w = __expf(v1.w - mx);

    float sm = v0.x + v0.y + v0.z + v0.w + v1.x + v1.y + v1.z + v1.w;
#pragma unroll
    for (int off = 16; off; off >>= 1)
        sm += __shfl_xor_sync(0xFFFFFFFFu, sm, off);

    const float inv = 1.0f / sm;
    v0.x *= inv; v0.y *= inv; v0.z *= inv; v0.w *= inv;
    v1.x *= inv; v1.y *= inv; v1.z *= inv; v1.w *= inv;

    *reinterpret_cast<float4*>(p + l * 4) = v0;
    *reinterpret_cast<float4*>(p + 128 + l * 4) = v1;
}

extern "C" void kernel_launch(void* const* d_in, const int* in_sizes, int n_in,
                              void* d_out, int out_size) {
    (void)in_sizes; (void)n_in; (void)out_size;
    const float* x  = (const float*)d_in[0];
    const float* Wq = (const float*)d_in[1];
    const float* bq = (const float*)d_in[2];
    const float* Wk = (const float*)d_in[3];
    const float* bk = (const float*)d_in[4];
    const float* Wv = (const float*)d_in[5];
    const float* bv = (const float*)d_in[6];
    const float* Wo = (const float*)d_in[7];
    const float* bo = (const float*)d_in[8];
    float* out = (float*)d_out;

    float *Q, *K, *V, *S, *O;
    cudaGetSymbolAddress((void**)&Q, g_Q);
    cudaGetSymbolAddress((void**)&K, g_K);
    cudaGetSymbolAddress((void**)&V, g_V);
    cudaGetSymbolAddress((void**)&S, g_S);
    cudaGetSymbolAddress((void**)&O, g_O);

    const dim3 blk(256);
    const int Mtok = 2 * 4096;              // 8192 token rows
    const long LSTRQ = (long)4096 * 2048;   // per-batch Q/O stride
    const long LSTRK = (long)4096 * 256;    // per-batch K/V stride
    const float iscale = 0.088388347648318447f;  // 1/sqrt(128)

    // 1-3) projections
    gemm_tf32<false><<<dim3(2048 / BN, Mtok / BM, 1), blk>>>(
        x, Wq, bq, Q, 2048, 2048, 2048, 2048,
        0, 0, 0, 0, 0, 0, 1, 0, 0, 0, 1, 1, 1.0f);
    gemm_tf32<false><<<dim3(256 / BN, Mtok / BM, 1), blk>>>(
        x, Wk, bk, K, 2048, 2048, 256, 256,
        0, 0, 0, 0, 0, 0, 1, 0, 0, 0, 1, 1, 1.0f);
    gemm_tf32<false><<<dim3(256 / BN, Mtok / BM, 1), blk>>>(
        x, Wv, bv, V, 2048, 2048, 256, 256,
        0, 0, 0, 0, 0, 0, 1, 0, 0, 0, 1, 1, 1.0f);

    // 4) S = scale * Qw @ Kw^T ; z = (b, h, n), 2*16*16 = 512 batches
    gemm_tf32<true><<<dim3(256 / BN, 256 / BM, 512), blk>>>(
        Q, K, nullptr, S, 128, 2048, 256, 256,
        LSTRQ, 128, (long)128 * 2048,
        LSTRK, 128, (long)128 * 256, 2,
        (long)256 * 65536, (long)16 * 65536, 65536,
        16, 16, iscale);

    // 5) softmax over 512*256 rows
    softmax_rows<<<(512 * 256) / 8, blk>>>(S);

    // 6) O = P @ Vw ; write into [B, t=n*256+q, h*128+d]
    gemm_tf32<false><<<dim3(128 / BN, 256 / BM, 512), blk>>>(
        S, V, nullptr, O, 256, 256, 256, 2048,
        (long)256 * 65536, (long)16 * 65536, 65536,
        LSTRK, 128, (long)128 * 256, 2,
        LSTRQ, 128, (long)256 * 2048,
        16, 16, 1.0f);

    // 7) out = O @ Wo + bo
    gemm_tf32<false><<<dim3(2048 / BN, Mtok / BM, 1), blk>>>(
        O, Wo, bo, out, 2048, 2048, 2048, 2048,
        0, 0, 0, 0, 0, 0, 1, 0, 0, 0, 1, 1, 1.0f);
}

// round 3
// speedup vs baseline: 1.0270x; 1.0270x over previous
#include <cuda_runtime.h>
#include <cstdint>

// ---------------------------------------------------------------------------
// EnhancedLocalAttentionWithGQA — round 2: cp.async 4-stage pipelined TF32 GEMM
//   64x64 warp tiles (8 warps), tf32 rounding hoisted out of the mainloop.
// Shapes: B=2, L=4096, C=2048, H=16, D=128, G=2 (g=h%2), W=256, stride 128.
// Only windows n=0..15 reach the output (reference reshape truncation).
// ---------------------------------------------------------------------------

#define DEV_INLINE __device__ __forceinline__

constexpr int BK  = 32;
constexpr int NST = 4;     // cp.async pipeline stages

// ---- scratch (device globals: allocation-free) ----
__device__ float g_Q [16777216];   // [B,L,H*D]
__device__ float g_K [ 2097152];   // [B,L,G*D]
__device__ float g_V [ 2097152];
__device__ float g_S [33554432];   // [(b*16+h)*16+n, 256, 256]
__device__ float g_O [16777216];   // [B,t,H*D]
__device__ float g_xr[16777216];   // tf32-rounded copies of inputs
__device__ float g_Wqr[4194304];
__device__ float g_Wkr[ 524288];
__device__ float g_Wvr[ 524288];
__device__ float g_Wor[4194304];

DEV_INLINE uint32_t f2tf(float f) {
    uint32_t u; asm("cvt.rna.tf32.f32 %0, %1;" : "=r"(u) : "f"(f)); return u;
}
DEV_INLINE float f2tff(float f) { return __uint_as_float(f2tf(f)); }

DEV_INLINE void mma_tf32(float c[4],
                         uint32_t a0, uint32_t a1, uint32_t a2, uint32_t a3,
                         uint32_t b0, uint32_t b1) {
    asm volatile(
        "mma.sync.aligned.m16n8k8.row.col.f32.tf32.tf32.f32 "
        "{%0,%1,%2,%3}, {%4,%5,%6,%7}, {%8,%9}, {%0,%1,%2,%3};\n"
        : "+f"(c[0]), "+f"(c[1]), "+f"(c[2]), "+f"(c[3])
        : "r"(a0), "r"(a1), "r"(a2), "r"(a3), "r"(b0), "r"(b1));
}

DEV_INLINE void cpa(uint32_t dst, const float* src) {
    asm volatile("cp.async.cg.shared.global [%0], [%1], 16;" :: "r"(dst), "l"(src));
}
DEV_INLINE void cp_commit() { asm volatile("cp.async.commit_group;"); }
template <int N> DEV_INLINE void cp_wait() {
    asm volatile("cp.async.wait_group %0;" :: "n"(N));
}

// ---------------------------------------------------------------------------
// Batched pipelined GEMM: C = alpha * A @ op(B) + bias.  All operands are
// already tf32-rounded fp32; the mma truncation is then exact.
//   BT=false: B is [K][N] row-major;  BT=true: B is [N][K] row-major.
// Batch z -> (b,h,n); B uses h % hmodB. Warp tile is always 64x64.
// ---------------------------------------------------------------------------
template <int BM, int BN, bool BT, bool ROUND>
__global__ __launch_bounds__(256) void gemm(
    const float* __restrict__ A, const float* __restrict__ B,
    const float* __restrict__ bias, float* __restrict__ C,
    int K, int lda, int ldb, int ldc,
    long A_sb, long A_sh, long A_sn,
    long B_sb, long B_sh, long B_sn, int hmodB,
    long C_sb, long C_sh, long C_sn,
    int NH, int NW, float alpha)
{
    constexpr int AST    = BK + 4;                      // A smem row stride (words)
    constexpr int AWORDS = BM * AST;
    constexpr int BST    = BT ? (BK + 4) : (BN + 8);    // B smem row stride
    constexpr int BWORDS = BT ? BN * (BK + 4) : BK * (BN + 8);

    extern __shared__ uint32_t sh[];
    uint32_t* As = sh;
    uint32_t* Bs = sh + NST * AWORDS;

    const int z  = blockIdx.z;
    const int bb = z / (NH * NW);
    const int hh = (z / NW) % NH;
    const int nw = z % NW;
    A += (size_t)bb * A_sb + (size_t)hh * A_sh + (size_t)nw * A_sn;
    B += (size_t)bb * B_sb + (size_t)(hh % hmodB) * B_sh + (size_t)nw * B_sn;
    C += (size_t)bb * C_sb + (size_t)hh * C_sh + (size_t)nw * C_sn;

    const int n0  = blockIdx.x * BN;
    const int m0  = blockIdx.y * BM;
    const int tid = threadIdx.x;
    const int w = tid >> 5, lane = tid & 31, g = lane >> 2, tg = lane & 3;
    constexpr int WARPS_M = BM / 64;
    const int wm = (w % WARPS_M) * 64;
    const int wn = (w / WARPS_M) * 64;

    const uint32_t sA = (uint32_t)__cvta_generic_to_shared(As);
    const uint32_t sB = (uint32_t)__cvta_generic_to_shared(Bs);
    const int KT = K / BK;

    auto load_tile = [&](int st, int kt) {
        const int k0 = kt * BK;
        {   // A tile: BM x 32
            const int c = tid & 7, r0 = tid >> 3;
            const uint32_t base = sA + (uint32_t)(st * AWORDS) * 4u;
#pragma unroll
            for (int i = 0; i < BM / 32; i++) {
                const int row = r0 + i * 32;
                cpa(base + (uint32_t)(row * AST + c * 4) * 4u,
                    A + (size_t)(m0 + row) * lda + k0 + c * 4);
            }
        }
        const uint32_t baseB = sB + (uint32_t)(st * BWORDS) * 4u;
        if (BT) {   // B tile: BN rows x 32 k
            const int c = tid & 7, r0 = tid >> 3;
#pragma unroll
            for (int i = 0; i < BN / 32; i++) {
                const int n = r0 + i * 32;
                cpa(baseB + (uint32_t)(n * (BK + 4) + c * 4) * 4u,
                    B + (size_t)(n0 + n) * ldb + k0 + c * 4);
            }
        } else {    // B tile: 32 k-rows x BN
            constexpr int CPR = BN / 4;      // 16B chunks per row
            constexpr int RPP = 256 / CPR;   // rows per pass
            const int c = tid % CPR, r0 = tid / CPR;
#pragma unroll
            for (int i = 0; i < BK / RPP; i++) {
                const int kr = r0 + i * RPP;
                cpa(baseB + (uint32_t)(kr * (BN + 8) + c * 4) * 4u,
                    B + (size_t)(k0 + kr) * ldb + n0 + c * 4);
            }
        }
    };

    float acc[4][8][4];
#pragma unroll
    for (int mi = 0; mi < 4; mi++)
#pragma unroll
        for (int ni = 0; ni < 8; ni++)
#pragma unroll
            for (int r = 0; r < 4; r++) acc[mi][ni][r] = 0.0f;

    // ---- prologue: fill NST-1 stages ----
#pragma unroll
    for (int s = 0; s < NST - 1; s++) {
        if (s < KT) load_tile(s, s);
        cp_commit();
    }
    cp_wait<NST - 2>();
    __syncthreads();

    // ---- mainloop ----
    for (int kt = 0; kt < KT; kt++) {
        const int nt = kt + NST - 1;
        if (nt < KT) load_tile(nt & (NST - 1), nt);
        cp_commit();

        const uint32_t* A_ = As + (size_t)(kt & (NST - 1)) * AWORDS;
        const uint32_t* B_ = Bs + (size_t)(kt & (NST - 1)) * BWORDS;
#pragma unroll
        for (int kk = 0; kk < BK / 8; kk++) {
            const int ks = kk * 8;
            uint32_t af[4][4];
#pragma unroll
            for (int mi = 0; mi < 4; mi++) {
                const int mb = wm + mi * 16;
                af[mi][0] = A_[(mb + g)     * AST + ks + tg];
                af[mi][1] = A_[(mb + g + 8) * AST + ks + tg];
                af[mi][2] = A_[(mb + g)     * AST + ks + tg + 4];
                af[mi][3] = A_[(mb + g + 8) * AST + ks + tg + 4];
            }
            uint32_t bf[8][2];
#pragma unroll
            for (int ni = 0; ni < 8; ni++) {
                const int nb = wn + ni * 8;
                if (BT) {
                    bf[ni][0] = B_[(nb + g) * (BK + 4) + ks + tg];
                    bf[ni][1] = B_[(nb + g) * (BK + 4) + ks + tg + 4];
                } else {
                    bf[ni][0] = B_[(ks + tg)     * (BN + 8) + nb + g];
                    bf[ni][1] = B_[(ks + tg + 4) * (BN + 8) + nb + g];
                }
            }
#pragma unroll
            for (int mi = 0; mi < 4; mi++)
#pragma unroll
                for (int ni = 0; ni < 8; ni++)
                    mma_tf32(acc[mi][ni], af[mi][0], af[mi][1], af[mi][2],
                             af[mi][3], bf[ni][0], bf[ni][1]);
        }
        cp_wait<NST - 2>();
        __syncthreads();
    }

    // ---- epilogue ----
#pragma unroll
    for (int mi = 0; mi < 4; mi++) {
        const int r0 = m0 + wm + mi * 16 + g;
#pragma unroll
        for (int ni = 0; ni < 8; ni++) {
            const int col = n0 + wn + ni * 8 + 2 * tg;
            float b0 = 0.0f, b1 = 0.0f;
            if (bias) { b0 = bias[col]; b1 = bias[col + 1]; }
            float v0 = acc[mi][ni][0] * alpha + b0;
            float v1 = acc[mi][ni][1] * alpha + b1;
            float v2 = acc[mi][ni][2] * alpha + b0;
            float v3 = acc[mi][ni][3] * alpha + b1;
            if (ROUND) { v0 = f2tff(v0); v1 = f2tff(v1); v2 = f2tff(v2); v3 = f2tff(v3); }
            *reinterpret_cast<float2*>(C + (size_t)r0 * ldc + col) = make_float2(v0, v1);
            *reinterpret_cast<float2*>(C + (size_t)(r0 + 8) * ldc + col) = make_float2(v2, v3);
        }
    }
}

// ---- tf32-round a buffer (pre-pass over inputs) ----
__global__ __launch_bounds__(256) void round_k(const float* __restrict__ s,
                                               float* __restrict__ d, long n) {
    const long i = ((long)blockIdx.x * 256 + threadIdx.x) * 4;
    if (i < n) {
        float4 v = *reinterpret_cast<const float4*>(s + i);
        v.x = f2tff(v.x); v.y = f2tff(v.y); v.z = f2tff(v.z); v.w = f2tff(v.w);
        *reinterpret_cast<float4*>(d + i) = v;
    }
}

// ---- row softmax over 256-float rows; one warp per row; tf32-round output ----
__global__ __launch_bounds__(256) void softmax_rows(float* __restrict__ S) {
    const int row = blockIdx.x * 8 + (threadIdx.x >> 5);
    const int l = threadIdx.x & 31;
    float* p = S + (size_t)row * 256;

    float4 v0 = *reinterpret_cast<const float4*>(p + l * 4);
    float4 v1 = *reinterpret_cast<const float4*>(p + 128 + l * 4);

    float mx = fmaxf(fmaxf(fmaxf(v0.x, v0.y), fmaxf(v0.z, v0.w)),
                     fmaxf(fmaxf(v1.x, v1.y), fmaxf(v1.z, v1.w)));
#pragma unroll
    for (int off = 16; off; off >>= 1)
        mx = fmaxf(mx, __shfl_xor_sync(0xFFFFFFFFu, mx, off));

    v0.x = __expf(v0.x - mx); v0.y = __expf(v0.y - mx);
    v0.z = __expf(v0.z - mx); v0.w = __expf(v0.w - mx);
    v1.x = __expf(v1.x - mx); v1.y = __expf(v1.y - mx);
    v1.z = __expf(v1.z - mx); v1.w = __expf(v1.w - mx);

    float sm = v0.x + v0.y + v0.z + v0.w + v1.x + v1.y + v1.z + v1.w;
#pragma unroll
    for (int off = 16; off; off >>= 1)
        sm += __shfl_xor_sync(0xFFFFFFFFu, sm, off);

    const float inv = 1.0f / sm;
    v0.x = f2tff(v0.x * inv); v0.y = f2tff(v0.y * inv);
    v0.z = f2tff(v0.z * inv); v0.w = f2tff(v0.w * inv);
    v1.x = f2tff(v1.x * inv); v1.y = f2tff(v1.y * inv);
    v1.z = f2tff(v1.z * inv); v1.w = f2tff(v1.w * inv);

    *reinterpret_cast<float4*>(p + l * 4) = v0;
    *reinterpret_cast<float4*>(p + 128 + l * 4) = v1;
}

extern "C" void kernel_launch(void* const* d_in, const int* in_sizes, int n_in,
                              void* d_out, int out_size) {
    (void)in_sizes; (void)n_in; (void)out_size;
    const float* x  = (const float*)d_in[0];
    const float* Wq = (const float*)d_in[1];
    const float* bq = (const float*)d_in[2];
    const float* Wk = (const float*)d_in[3];
    const float* bk = (const float*)d_in[4];
    const float* Wv = (const float*)d_in[5];
    const float* bv = (const float*)d_in[6];
    const float* Wo = (const float*)d_in[7];
    const float* bo = (const float*)d_in[8];
    float* out = (float*)d_out;

    float *Q, *K, *V, *S, *O, *xr, *Wqr, *Wkr, *Wvr, *Wor;
    cudaGetSymbolAddress((void**)&Q,  g_Q);
    cudaGetSymbolAddress((void**)&K,  g_K);
    cudaGetSymbolAddress((void**)&V,  g_V);
    cudaGetSymbolAddress((void**)&S,  g_S);
    cudaGetSymbolAddress((void**)&O,  g_O);
    cudaGetSymbolAddress((void**)&xr, g_xr);
    cudaGetSymbolAddress((void**)&Wqr, g_Wqr);
    cudaGetSymbolAddress((void**)&Wkr, g_Wkr);
    cudaGetSymbolAddress((void**)&Wvr, g_Wvr);
    cudaGetSymbolAddress((void**)&Wor, g_Wor);

    constexpr int SZ_G1N = NST * (128 * 36 + 32 * (256 + 8)) * 4;  // 208896
    constexpr int SZ_G1T = NST * (128 * 36 + 256 * 36) * 4;        // 221184
    constexpr int SZ_G2N = NST * (256 * 36 + 32 * (128 + 8)) * 4;  // 217088

    cudaFuncSetAttribute((const void*)gemm<128, 256, false, true>,
                         cudaFuncAttributeMaxDynamicSharedMemorySize, SZ_G1N);
    cudaFuncSetAttribute((const void*)gemm<128, 256, false, false>,
                         cudaFuncAttributeMaxDynamicSharedMemorySize, SZ_G1N);
    cudaFuncSetAttribute((const void*)gemm<128, 256, true, false>,
                         cudaFuncAttributeMaxDynamicSharedMemorySize, SZ_G1T);
    cudaFuncSetAttribute((const void*)gemm<256, 128, false, true>,
                         cudaFuncAttributeMaxDynamicSharedMemorySize, SZ_G2N);

    const dim3 blk(256);
    const long LSTRQ = 4096L * 2048;   // per-batch Q/O stride
    const long LSTRK = 4096L * 256;    // per-batch K/V stride
    const float iscale = 0.088388347648318447f;  // 1/sqrt(128)

    // 0) tf32-round inputs into scratch
    round_k<<<16384, blk>>>(x,  xr,  16777216);
    round_k<<< 4096, blk>>>(Wq, Wqr,  4194304);
    round_k<<<  512, blk>>>(Wk, Wkr,   524288);
    round_k<<<  512, blk>>>(Wv, Wvr,   524288);
    round_k<<< 4096, blk>>>(Wo, Wor,  4194304);

    // 1-3) projections (outputs tf32-rounded)
    gemm<128, 256, false, true><<<dim3(8, 64, 1), blk, SZ_G1N>>>(
        xr, Wqr, bq, Q, 2048, 2048, 2048, 2048,
        0, 0, 0, 0, 0, 0, 1, 0, 0, 0, 1, 1, 1.0f);
    gemm<128, 256, false, true><<<dim3(1, 64, 1), blk, SZ_G1N>>>(
        xr, Wkr, bk, K, 2048, 2048, 256, 256,
        0, 0, 0, 0, 0, 0, 1, 0, 0, 0, 1, 1, 1.0f);
    gemm<128, 256, false, true><<<dim3(1, 64, 1), blk, SZ_G1N>>>(
        xr, Wvr, bv, V, 2048, 2048, 256, 256,
        0, 0, 0, 0, 0, 0, 1, 0, 0, 0, 1, 1, 1.0f);

    // 4) S = scale * Qw @ Kw^T ; z = (b,h,n) -> 512 batches of 256x256, K=128
    gemm<128, 256, true, false><<<dim3(1, 2, 512), blk, SZ_G1T>>>(
        Q, K, nullptr, S, 128, 2048, 256, 256,
        LSTRQ, 128, 128L * 2048,
        LSTRK, 128, 128L * 256, 2,
        256L * 65536, 16L * 65536, 65536,
        16, 16, iscale);

    // 5) softmax over 512*256 rows (tf32-rounds P)
    softmax_rows<<<(512 * 256) / 8, blk>>>(S);

    // 6) O = P @ Vw ; 512 batches of 256x128, K=256 (output tf32-rounded)
    gemm<256, 128, false, true><<<dim3(1, 1, 512), blk, SZ_G2N>>>(
        S, V, nullptr, O, 256, 256, 256, 2048,
        256L * 65536, 16L * 65536, 65536,
        LSTRK, 128, 128L * 256, 2,
        LSTRQ, 128, 256L * 2048,
        16, 16, 1.0f);

    // 7) out = O @ Wo + bo (fp32 output)
    gemm<128, 256, false, false><<<dim3(8, 64, 1), blk, SZ_G1N>>>(
        O, Wor, bo, out, 2048, 2048, 2048, 2048,
        0, 0, 0, 0, 0, 0, 1, 0, 0, 0, 1, 1, 1.0f);
}

// round 4
// speedup vs baseline: 1.0312x; 1.0041x over previous
#include <cuda_runtime.h>
#include <cstdint>

// ---------------------------------------------------------------------------
// EnhancedLocalAttentionWithGQA — round 2: cp.async 4-stage pipelined TF32 GEMM
//   64x64 warp tiles (8 warps), tf32 rounding hoisted out of the mainloop.
// Shapes: B=2, L=4096, C=2048, H=16, D=128, G=2 (g=h%2), W=256, stride 128.
// Only windows n=0..15 reach the output (reference reshape truncation).
// ---------------------------------------------------------------------------

#define DEV_INLINE __device__ __forceinline__

constexpr int BK  = 32;
constexpr int NST = 4;     // cp.async pipeline stages

// ---- scratch (device globals: allocation-free) ----
__device__ float g_Q [16777216];   // [B,L,H*D]
__device__ float g_K [ 2097152];   // [B,L,G*D]
__device__ float g_V [ 2097152];
__device__ float g_S [33554432];   // [(b*16+h)*16+n, 256, 256]
__device__ float g_O [16777216];   // [B,t,H*D]
__device__ float g_xr[16777216];   // tf32-rounded copies of inputs
__device__ float g_Wqr[4194304];
__device__ float g_Wkr[ 524288];
__device__ float g_Wvr[ 524288];
__device__ float g_Wor[4194304];

DEV_INLINE uint32_t f2tf(float f) {
    uint32_t u; asm("cvt.rna.tf32.f32 %0, %1;" : "=r"(u) : "f"(f)); return u;
}
DEV_INLINE float f2tff(float f) { return __uint_as_float(f2tf(f)); }

DEV_INLINE void mma_tf32(float c[4],
                         uint32_t a0, uint32_t a1, uint32_t a2, uint32_t a3,
                         uint32_t b0, uint32_t b1) {
    asm volatile(
        "mma.sync.aligned.m16n8k8.row.col.f32.tf32.tf32.f32 "
        "{%0,%1,%2,%3}, {%4,%5,%6,%7}, {%8,%9}, {%0,%1,%2,%3};\n"
        : "+f"(c[0]), "+f"(c[1]), "+f"(c[2]), "+f"(c[3])
        : "r"(a0), "r"(a1), "r"(a2), "r"(a3), "r"(b0), "r"(b1));
}

DEV_INLINE void cpa(uint32_t dst, const float* src) {
    asm volatile("cp.async.cg.shared.global [%0], [%1], 16;" :: "r"(dst), "l"(src));
}
DEV_INLINE void cp_commit() { asm volatile("cp.async.commit_group;"); }
template <int N> DEV_INLINE void cp_wait() {
    asm volatile("cp.async.wait_group %0;" :: "n"(N));
}

// ---------------------------------------------------------------------------
// Batched pipelined GEMM: C = alpha * A @ op(B) + bias.  All operands are
// already tf32-rounded fp32; the mma truncation is then exact.
//   BT=false: B is [K][N] row-major;  BT=true: B is [N][K] row-major.
// Batch z -> (b,h,n); B uses h % hmodB. Warp tile is always 64x64.
// ---------------------------------------------------------------------------
template <int BM, int BN, bool BT, bool ROUND>
__global__ __launch_bounds__(256) void gemm(
    const float* __restrict__ A, const float* __restrict__ B,
    const float* __restrict__ bias, float* __restrict__ C,
    int K, int lda, int ldb, int ldc,
    long A_sb, long A_sh, long A_sn,
    long B_sb, long B_sh, long B_sn, int hmodB,
    long C_sb, long C_sh, long C_sn,
    int NH, int NW, float alpha)
{
    constexpr int AST    = BK + 4;                      // A smem row stride (words)
    constexpr int AWORDS = BM * AST;
    constexpr int BST    = BT ? (BK + 4) : (BN + 8);    // B smem row stride
    constexpr int BWORDS = BT ? BN * (BK + 4) : BK * (BN + 8);

    extern __shared__ uint32_t sh[];
    uint32_t* As = sh;
    uint32_t* Bs = sh + NST * AWORDS;

    const int z  = blockIdx.z;
    const int bb = z / (NH * NW);
    const int hh = (z / NW) % NH;
    const int nw = z % NW;
    A += (size_t)bb * A_sb + (size_t)hh * A_sh + (size_t)nw * A_sn;
    B += (size_t)bb * B_sb + (size_t)(hh % hmodB) * B_sh + (size_t)nw * B_sn;
    C += (size_t)bb * C_sb + (size_t)hh * C_sh + (size_t)nw * C_sn;

    const int n0  = blockIdx.x * BN;
    const int m0  = blockIdx.y * BM;
    const int tid = threadIdx.x;
    const int w = tid >> 5, lane = tid & 31, g = lane >> 2, tg = lane & 3;
    constexpr int WARPS_M = BM / 64;
    const int wm = (w % WARPS_M) * 64;
    const int wn = (w / WARPS_M) * 64;

    const uint32_t sA = (uint32_t)__cvta_generic_to_shared(As);
    const uint32_t sB = (uint32_t)__cvta_generic_to_shared(Bs);
    const int KT = K / BK;

    auto load_tile = [&](int st, int kt) {
        const int k0 = kt * BK;
        {   // A tile: BM x 32
            const int c = tid & 7, r0 = tid >> 3;
            const uint32_t base = sA + (uint32_t)(st * AWORDS) * 4u;
#pragma unroll
            for (int i = 0; i < BM / 32; i++) {
                const int row = r0 + i * 32;
                cpa(base + (uint32_t)(row * AST + c * 4) * 4u,
                    A + (size_t)(m0 + row) * lda + k0 + c * 4);
            }
        }
        const uint32_t baseB = sB + (uint32_t)(st * BWORDS) * 4u;
        if (BT) {   // B tile: BN rows x 32 k
            const int c = tid & 7, r0 = tid >> 3;
#pragma unroll
            for (int i = 0; i < BN / 32; i++) {
                const int n = r0 + i * 32;
                cpa(baseB + (uint32_t)(n * (BK + 4) + c * 4) * 4u,
                    B + (size_t)(n0 + n) * ldb + k0 + c * 4);
            }
        } else {    // B tile: 32 k-rows x BN
            constexpr int CPR = BN / 4;      // 16B chunks per row
            constexpr int RPP = 256 / CPR;   // rows per pass
            const int c = tid % CPR, r0 = tid / CPR;
#pragma unroll
            for (int i = 0; i < BK / RPP; i++) {
                const int kr = r0 + i * RPP;
                cpa(baseB + (uint32_t)(kr * (BN + 8) + c * 4) * 4u,
                    B + (size_t)(k0 + kr) * ldb + n0 + c * 4);
            }
        }
    };

    float acc[4][8][4];
#pragma unroll
    for (int mi = 0; mi < 4; mi++)
#pragma unroll
        for (int ni = 0; ni < 8; ni++)
#pragma unroll
            for (int r = 0; r < 4; r++) acc[mi][ni][r] = 0.0f;

    // ---- prologue: fill NST-1 stages ----
#pragma unroll
    for (int s = 0; s < NST - 1; s++) {
        if (s < KT) load_tile(s, s);
        cp_commit();
    }
    cp_wait<NST - 2>();
    __syncthreads();

    // ---- mainloop ----
    for (int kt = 0; kt < KT; kt++) {
        const int nt = kt + NST - 1;
        if (nt < KT) load_tile(nt & (NST - 1), nt);
        cp_commit();

        const uint32_t* A_ = As + (size_t)(kt & (NST - 1)) * AWORDS;
        const uint32_t* B_ = Bs + (size_t)(kt & (NST - 1)) * BWORDS;
#pragma unroll
        for (int kk = 0; kk < BK / 8; kk++) {
            const int ks = kk * 8;
            uint32_t af[4][4];
#pragma unroll
            for (int mi = 0; mi < 4; mi++) {
                const int mb = wm + mi * 16;
                af[mi][0] = A_[(mb + g)     * AST + ks + tg];
                af[mi][1] = A_[(mb + g + 8) * AST + ks + tg];
                af[mi][2] = A_[(mb + g)     * AST + ks + tg + 4];
                af[mi][3] = A_[(mb + g + 8) * AST + ks + tg + 4];
            }
            uint32_t bf[8][2];
#pragma unroll
            for (int ni = 0; ni < 8; ni++) {
                const int nb = wn + ni * 8;
                if (BT) {
                    bf[ni][0] = B_[(nb + g) * (BK + 4) + ks + tg];
                    bf[ni][1] = B_[(nb + g) * (BK + 4) + ks + tg + 4];
                } else {
                    bf[ni][0] = B_[(ks + tg)     * (BN + 8) + nb + g];
                    bf[ni][1] = B_[(ks + tg + 4) * (BN + 8) + nb + g];
                }
            }
#pragma unroll
            for (int mi = 0; mi < 4; mi++)
#pragma unroll
                for (int ni = 0; ni < 8; ni++)
                    mma_tf32(acc[mi][ni], af[mi][0], af[mi][1], af[mi][2],
                             af[mi][3], bf[ni][0], bf[ni][1]);
        }
        cp_wait<NST - 2>();
        __syncthreads();
    }

    // ---- epilogue ----
#pragma unroll
    for (int mi = 0; mi < 4; mi++) {
        const int r0 = m0 + wm + mi * 16 + g;
#pragma unroll
        for (int ni = 0; ni < 8; ni++) {
            const int col = n0 + wn + ni * 8 + 2 * tg;
            float b0 = 0.0f, b1 = 0.0f;
            if (bias) { b0 = bias[col]; b1 = bias[col + 1]; }
            float v0 = acc[mi][ni][0] * alpha + b0;
            float v1 = acc[mi][ni][1] * alpha + b1;
            float v2 = acc[mi][ni][2] * alpha + b0;
            float v3 = acc[mi][ni][3] * alpha + b1;
            if (ROUND) { v0 = f2tff(v0); v1 = f2tff(v1); v2 = f2tff(v2); v3 = f2tff(v3); }
            *reinterpret_cast<float2*>(C + (size_t)r0 * ldc + col) = make_float2(v0, v1);
            *reinterpret_cast<float2*>(C + (size_t)(r0 + 8) * ldc + col) = make_float2(v2, v3);
        }
    }
}

// ---- tf32-round a buffer (pre-pass over inputs) ----
__global__ __launch_bounds__(256) void round_k(const float* __restrict__ s,
                                               float* __restrict__ d, long n) {
    const long i = ((long)blockIdx.x * 256 + threadIdx.x) * 4;
    if (i < n) {
        float4 v = *reinterpret_cast<const float4*>(s + i);
        v.x = f2tff(v.x); v.y = f2tff(v.y); v.z = f2tff(v.z); v.w = f2tff(v.w);
        *reinterpret_cast<float4*>(d + i) = v;
    }
}

// ---- row softmax over 256-float rows; one warp per row; tf32-round output ----
__global__ __launch_bounds__(256) void softmax_rows(float* __restrict__ S) {
    const int row = blockIdx.x * 8 + (threadIdx.x >> 5);
    const int l = threadIdx.x & 31;
    float* p = S + (size_t)row * 256;

    float4 v0 = *reinterpret_cast<const float4*>(p + l * 4);
    float4 v1 = *reinterpret_cast<const float4*>(p + 128 + l * 4);

    float mx = fmaxf(fmaxf(fmaxf(v0.x, v0.y), fmaxf(v0.z, v0.w)),
                     fmaxf(fmaxf(v1.x, v1.y), fmaxf(v1.z, v1.w)));
#pragma unroll
    for (int off = 16; off; off >>= 1)
        mx = fmaxf(mx, __shfl_xor_sync(0xFFFFFFFFu, mx, off));

    v0.x = __expf(v0.x - mx); v0.y = __expf(v0.y - mx);
    v0.z = __expf(v0.z - mx); v0.w = __expf(v0.w - mx);
    v1.x = __expf(v1.x - mx); v1.y = __expf(v1.y - mx);
    v1.z = __expf(v1.z - mx); v1.w = __expf(v1.w - mx);

    float sm = v0.x + v0.y + v0.z + v0.w + v1.x + v1.y + v1.z + v1.w;
#pragma unroll
    for (int off = 16; off; off >>= 1)
        sm += __shfl_xor_sync(0xFFFFFFFFu, sm, off);

    const float inv = 1.0f / sm;
    v0.x = f2tff(v0.x * inv); v0.y = f2tff(v0.y * inv);
    v0.z = f2tff(v0.z * inv); v0.w = f2tff(v0.w * inv);
    v1.x = f2tff(v1.x * inv); v1.y = f2tff(v1.y * inv);
    v1.z = f2tff(v1.z * inv); v1.w = f2tff(v1.w * inv);

    *reinterpret_cast<float4*>(p + l * 4) = v0;
    *reinterpret_cast<float4*>(p + 128 + l * 4) = v1;
}

extern "C" void kernel_launch(void* const* d_in, const int* in_sizes, int n_in,
                              void* d_out, int out_size) {
    (void)in_sizes; (void)n_in; (void)out_size;
    const float* x  = (const float*)d_in[0];
    const float* Wq = (const float*)d_in[1];
    const float* bq = (const float*)d_in[2];
    const float* Wk = (const float*)d_in[3];
    const float* bk = (const float*)d_in[4];
    const float* Wv = (const float*)d_in[5];
    const float* bv = (const float*)d_in[6];
    const float* Wo = (const float*)d_in[7];
    const float* bo = (const float*)d_in[8];
    float* out = (float*)d_out;

    float *Q, *K, *V, *S, *O, *xr, *Wqr, *Wkr, *Wvr, *Wor;
    cudaGetSymbolAddress((void**)&Q,  g_Q);
    cudaGetSymbolAddress((void**)&K,  g_K);
    cudaGetSymbolAddress((void**)&V,  g_V);
    cudaGetSymbolAddress((void**)&S,  g_S);
    cudaGetSymbolAddress((void**)&O,  g_O);
    cudaGetSymbolAddress((void**)&xr, g_xr);
    cudaGetSymbolAddress((void**)&Wqr, g_Wqr);
    cudaGetSymbolAddress((void**)&Wkr, g_Wkr);
    cudaGetSymbolAddress((void**)&Wvr, g_Wvr);
    cudaGetSymbolAddress((void**)&Wor, g_Wor);

    constexpr int SZ_G1N = NST * (128 * 36 + 32 * (256 + 8)) * 4;  // 208896
    constexpr int SZ_G1T = NST * (128 * 36 + 256 * 36) * 4;        // 221184
    constexpr int SZ_G2N = NST * (256 * 36 + 32 * (128 + 8)) * 4;  // 217088

    cudaFuncSetAttribute((const void*)gemm<128, 256, false, true>,
                         cudaFuncAttributeMaxDynamicSharedMemorySize, SZ_G1N);
    cudaFuncSetAttribute((const void*)gemm<128, 256, false, false>,
                         cudaFuncAttributeMaxDynamicSharedMemorySize, SZ_G1N);
    cudaFuncSetAttribute((const void*)gemm<128, 256, true, false>,
                         cudaFuncAttributeMaxDynamicSharedMemorySize, SZ_G1T);
    cudaFuncSetAttribute((const void*)gemm<256, 128, false, true>,
                         cudaFuncAttributeMaxDynamicSharedMemorySize, SZ_G2N);

    const dim3 blk(256);
    const long LSTRQ = 4096L * 2048;   // per-batch Q/O stride
    const long LSTRK = 4096L * 256;    // per-batch K/V stride
    const float iscale = 0.088388347648318447f;  // 1/sqrt(128)

    // 0) tf32-round inputs into scratch
    round_k<<<16384, blk>>>(x,  xr,  16777216);
    round_k<<< 4096, blk>>>(Wq, Wqr,  4194304);
    round_k<<<  512, blk>>>(Wk, Wkr,   524288);
    round_k<<<  512, blk>>>(Wv, Wvr,   524288);
    round_k<<< 4096, blk>>>(Wo, Wor,  4194304);

    // 1-3) projections (outputs tf32-rounded)
    gemm<128, 256, false, true><<<dim3(8, 64, 1), blk, SZ_G1N>>>(
        xr, Wqr, bq, Q, 2048, 2048, 2048, 2048,
        0, 0, 0, 0, 0, 0, 1, 0, 0, 0, 1, 1, 1.0f);
    gemm<128, 256, false, true><<<dim3(1, 64, 1), blk, SZ_G1N>>>(
        xr, Wkr, bk, K, 2048, 2048, 256, 256,
        0, 0, 0, 0, 0, 0, 1, 0, 0, 0, 1, 1, 1.0f);
    gemm<128, 256, false, true><<<dim3(1, 64, 1), blk, SZ_G1N>>>(
        xr, Wvr, bv, V, 2048, 2048, 256, 256,
        0, 0, 0, 0, 0, 0, 1, 0, 0, 0, 1, 1, 1.0f);

    // 4) S = scale * Qw @ Kw^T ; z = (b,h,n) -> 512 batches of 256x256, K=128
    gemm<128, 256, true, false><<<dim3(1, 2, 512), blk, SZ_G1T>>>(
        Q, K, nullptr, S, 128, 2048, 256, 256,
        LSTRQ, 128, 128L * 2048,
        LSTRK, 128, 128L * 256, 2,
        256L * 65536, 16L * 65536, 65536,
        16, 16, iscale);

    // 5) softmax over 512*256 rows (tf32-rounds P)
    softmax_rows<<<(512 * 256) / 8, blk>>>(S);

    // 6) O = P @ Vw ; 512 batches of 256x128, K=256 (output tf32-rounded)
    gemm<256, 128, false, true><<<dim3(1, 1, 512), blk, SZ_G2N>>>(
        S, V, nullptr, O, 256, 256, 256, 2048,
        256L * 65536, 16L * 65536, 65536,
        LSTRK, 128, 128L * 256, 2,
        LSTRQ, 128, 256L * 2048,
        16, 16, 1.0f);

    // 7) out = O @ Wo + bo (fp32 output)
    gemm<128, 256, false, false><<<dim3(8, 64, 1), blk, SZ_G1N>>>(
        O, Wor, bo, out, 2048, 2048, 2048, 2048,
        0, 0, 0, 0, 0, 0, 1, 0, 0, 0, 1, 1, 1.0f);
}

// round 9
// speedup vs baseline: 1.6325x; 1.5831x over previous
#include <cuda_runtime.h>
#include <cuda_fp16.h>
#include <cstdint>

// ---------------------------------------------------------------------------
// EnhancedLocalAttentionWithGQA — round 6: fp16 m16n8k16 mma.sync (compute_100
// safe), cp.async 4-stage pipeline, fp16 intermediates, fp32 scores/softmax.
// Shapes: B=2, L=4096, C=2048, H=16, D=128, G=2 (g=h%2), W=256, stride 128.
// Only windows n=0..15 reach the output (reference reshape truncation).
// ---------------------------------------------------------------------------

#define DEV_INLINE __device__ __forceinline__

constexpr int BK  = 32;    // K halves per stage (2 x k16 mma steps)
constexpr int NST = 4;     // cp.async pipeline stages

// ---- scratch (device globals: allocation-free) ----
__device__ __half g_xh [16777216];  // x             [8192][2048] fp16
__device__ __half g_Qh [16777216];  // Q             [B,L,H*D]
__device__ __half g_Kh [ 2097152];  // K             [B,L,G*D]
__device__ __half g_VTh[ 2097152];  // V transposed  [B,G,128 d][4096 tok]
__device__ __half g_Ph [33554432];  // P (softmaxed) [z][256][256]
__device__ __half g_Oh [16777216];  // O             [B,t,H*D]
__device__ __half g_WqT[ 4194304];  // weights transposed [N][K] fp16
__device__ __half g_WkT[  524288];
__device__ __half g_WvT[  524288];
__device__ __half g_WoT[ 4194304];
__device__ float  g_Sf [33554432];  // scores fp32   [z][256][256]

DEV_INLINE void mma_f16(float c[4],
                        uint32_t a0, uint32_t a1, uint32_t a2, uint32_t a3,
                        uint32_t b0, uint32_t b1) {
    asm volatile(
        "mma.sync.aligned.m16n8k16.row.col.f32.f16.f16.f32 "
        "{%0,%1,%2,%3}, {%4,%5,%6,%7}, {%8,%9}, {%0,%1,%2,%3};\n"
        : "+f"(c[0]), "+f"(c[1]), "+f"(c[2]), "+f"(c[3])
        : "r"(a0), "r"(a1), "r"(a2), "r"(a3), "r"(b0), "r"(b1));
}

DEV_INLINE void cpa(uint32_t dst, const void* src) {
    asm volatile("cp.async.cg.shared.global [%0], [%1], 16;" :: "r"(dst), "l"(src));
}
DEV_INLINE void cp_commit() { asm volatile("cp.async.commit_group;"); }
template <int N> DEV_INLINE void cp_wait() {
    asm volatile("cp.async.wait_group %0;" :: "n"(N));
}

// ---------------------------------------------------------------------------
// Batched pipelined fp16 GEMM: C = epilogue(alpha * A @ B^T [+ bias]).
//   A: [M][K] row-major fp16.  B: [N][K] row-major fp16 (always "BT").
// Batch z -> (b,h,n); B uses h % hmodB.
// EPI: 0 = fp32 out (+bias), 1 = fp16 out (+bias), 2 = fp16 V-transpose
//      scatter (+bias), 3 = fp32 out * alpha (scores), 4 = fp16 out.
// ---------------------------------------------------------------------------
template <int BM, int BN, int EPI>
__global__ __launch_bounds__(256, 1) void gemm_h(
    const __half* __restrict__ A, const __half* __restrict__ B,
    const float* __restrict__ bias, void* __restrict__ Cv,
    int K, int lda, int ldb, int ldc,
    long A_sb, long A_sh, long A_sn,
    long B_sb, long B_sh, long B_sn, int hmodB,
    long C_sb, long C_sh, long C_sn,
    int NH, int NW, float alpha)
{
    constexpr int AW     = BK / 2 + 4;     // 20 words/row (16 data + 4 pad)
    constexpr int AWORDS = BM * AW;
    constexpr int BWORDS = BN * AW;

    extern __shared__ uint32_t sh[];
    uint32_t* As = sh;
    uint32_t* Bs = sh + NST * AWORDS;

    const int z  = blockIdx.z;
    const int bb = z / (NH * NW);
    const int hh = (z / NW) % NH;
    const int nw = z % NW;
    A += (size_t)bb * A_sb + (size_t)hh * A_sh + (size_t)nw * A_sn;
    B += (size_t)bb * B_sb + (size_t)(hh % hmodB) * B_sh + (size_t)nw * B_sn;

    const int n0  = blockIdx.x * BN;
    const int m0  = blockIdx.y * BM;
    const int tid = threadIdx.x;
    const int w = tid >> 5, lane = tid & 31, g = lane >> 2, tg = lane & 3;
    constexpr int WARPS_M = BM / 64;
    const int wm = (w % WARPS_M) * 64;
    const int wn = (w / WARPS_M) * 64;

    const uint32_t sA = (uint32_t)__cvta_generic_to_shared(As);
    const uint32_t sB = (uint32_t)__cvta_generic_to_shared(Bs);
    const int KT = K / BK;

    auto load_tile = [&](int st, int kt) {
        const int k0 = kt * BK;
        const uint32_t ba = sA + (uint32_t)(st * AWORDS) * 4u;
#pragma unroll
        for (int i = 0; i < BM / 64; i++) {        // BM*4 chunks of 16B
            const int idx = i * 256 + tid;
            const int row = idx >> 2, c = idx & 3;
            cpa(ba + (uint32_t)(row * AW + c * 4) * 4u,
                A + (size_t)(m0 + row) * lda + k0 + c * 8);
        }
        const uint32_t bbs = sB + (uint32_t)(st * BWORDS) * 4u;
#pragma unroll
        for (int i = 0; i < BN / 64; i++) {
            const int idx = i * 256 + tid;
            const int row = idx >> 2, c = idx & 3;
            cpa(bbs + (uint32_t)(row * AW + c * 4) * 4u,
                B + (size_t)(n0 + row) * ldb + k0 + c * 8);
        }
    };

    float acc[4][8][4];
#pragma unroll
    for (int mi = 0; mi < 4; mi++)
#pragma unroll
        for (int ni = 0; ni < 8; ni++)
#pragma unroll
            for (int r = 0; r < 4; r++) acc[mi][ni][r] = 0.0f;

    // ---- prologue ----
#pragma unroll
    for (int s = 0; s < NST - 1; s++) {
        if (s < KT) load_tile(s, s);
        cp_commit();
    }
    cp_wait<NST - 2>();
    __syncthreads();

    // ---- mainloop (identical ordering to the proven round-2 kernel) ----
    for (int kt = 0; kt < KT; kt++) {
        const int nt = kt + NST - 1;
        if (nt < KT) load_tile(nt & (NST - 1), nt);
        cp_commit();

        const uint32_t* A_ = As + (size_t)(kt & (NST - 1)) * AWORDS;
        const uint32_t* B_ = Bs + (size_t)(kt & (NST - 1)) * BWORDS;
#pragma unroll
        for (int ks = 0; ks < BK / 16; ks++) {     // 2 k16 steps
            const int kw = ks * 8;
            uint32_t af[4][4];
#pragma unroll
            for (int mi = 0; mi < 4; mi++) {
                const int mb = wm + mi * 16;
                af[mi][0] = A_[(mb + g)     * AW + kw + tg];
                af[mi][1] = A_[(mb + g + 8) * AW + kw + tg];
                af[mi][2] = A_[(mb + g)     * AW + kw + tg + 4];
                af[mi][3] = A_[(mb + g + 8) * AW + kw + tg + 4];
            }
            uint32_t bf[8][2];
#pragma unroll
            for (int ni = 0; ni < 8; ni++) {
                const int nb = wn + ni * 8;
                bf[ni][0] = B_[(nb + g) * AW + kw + tg];
                bf[ni][1] = B_[(nb + g) * AW + kw + tg + 4];
            }
#pragma unroll
            for (int mi = 0; mi < 4; mi++)
#pragma unroll
                for (int ni = 0; ni < 8; ni++)
                    mma_f16(acc[mi][ni], af[mi][0], af[mi][1], af[mi][2],
                            af[mi][3], bf[ni][0], bf[ni][1]);
        }
        cp_wait<NST - 2>();
        __syncthreads();
    }

    // ---- epilogue ----
    const int bbat = m0 >> 12;                       // batch from global row
#pragma unroll
    for (int mi = 0; mi < 4; mi++) {
        const int r0 = m0 + wm + mi * 16 + g;
#pragma unroll
        for (int ni = 0; ni < 8; ni++) {
            const int col = n0 + wn + ni * 8 + 2 * tg;
            float b0 = 0.0f, b1 = 0.0f;
            if (EPI == 0 || EPI == 1 || EPI == 2) {
                if (bias) { b0 = bias[col]; b1 = bias[col + 1]; }
            }
            const float v0 = acc[mi][ni][0] * alpha + b0;
            const float v1 = acc[mi][ni][1] * alpha + b1;
            const float v2 = acc[mi][ni][2] * alpha + b0;
            const float v3 = acc[mi][ni][3] * alpha + b1;

            if (EPI == 0 || EPI == 3) {
                float* C = (float*)Cv +
                    (size_t)bb * C_sb + (size_t)hh * C_sh + (size_t)nw * C_sn;
                *reinterpret_cast<float2*>(C + (size_t)r0 * ldc + col) =
                    make_float2(v0, v1);
                *reinterpret_cast<float2*>(C + (size_t)(r0 + 8) * ldc + col) =
                    make_float2(v2, v3);
            } else if (EPI == 2) {
                // VT[b][g][d][token]: d = col&127, gg = col>>7
                __half* C = (__half*)Cv;
                const int gg = col >> 7, d = col & 127;
                const size_t base = ((size_t)(bbat * 2 + gg) * 128 + d) * 4096;
                const int tl0 = r0 & 4095, tl1 = (r0 + 8) & 4095;
                C[base + tl0]        = __float2half(v0);
                C[base + 4096 + tl0] = __float2half(v1);
                C[base + tl1]        = __float2half(v2);
                C[base + 4096 + tl1] = __float2half(v3);
            } else {
                __half* C = (__half*)Cv +
                    (size_t)bb * C_sb + (size_t)hh * C_sh + (size_t)nw * C_sn;
                *reinterpret_cast<__half2*>(C + (size_t)r0 * ldc + col) =
                    __floats2half2_rn(v0, v1);
                *reinterpret_cast<__half2*>(C + (size_t)(r0 + 8) * ldc + col) =
                    __floats2half2_rn(v2, v3);
            }
        }
    }
}

// ---- fp32 -> fp16 conversion ----
__global__ __launch_bounds__(256) void conv_h(const float* __restrict__ s,
                                              __half* __restrict__ d, long n) {
    const long i = ((long)blockIdx.x * 256 + threadIdx.x) * 4;
    if (i < n) {
        const float4 v = *reinterpret_cast<const float4*>(s + i);
        __half2* p = reinterpret_cast<__half2*>(d + i);
        p[0] = __floats2half2_rn(v.x, v.y);
        p[1] = __floats2half2_rn(v.z, v.w);
    }
}

// ---- transpose [K][N] fp32 -> [N][K] fp16 ----
__global__ __launch_bounds__(256) void transpose_h(
    const float* __restrict__ src, __half* __restrict__ dst, int K, int N) {
    __shared__ float t[32][33];
    const int bx = blockIdx.x * 32;   // N
    const int by = blockIdx.y * 32;   // K
    const int tx = threadIdx.x & 31, ty = threadIdx.x >> 5;
#pragma unroll
    for (int i = 0; i < 4; i++)
        t[ty + i * 8][tx] = src[(size_t)(by + ty + i * 8) * N + bx + tx];
    __syncthreads();
#pragma unroll
    for (int i = 0; i < 4; i++)
        dst[(size_t)(bx + ty + i * 8) * K + by + tx] =
            __float2half(t[tx][ty + i * 8]);
}

// ---- row softmax: fp32 scores (scale pre-applied) -> fp16 P, 1 warp/row ----
__global__ __launch_bounds__(256) void softmax_h(const float* __restrict__ S,
                                                 __half* __restrict__ P) {
    const int row = blockIdx.x * 8 + (threadIdx.x >> 5);
    const int l = threadIdx.x & 31;
    const float* p = S + (size_t)row * 256;

    float4 v0 = *reinterpret_cast<const float4*>(p + l * 4);
    float4 v1 = *reinterpret_cast<const float4*>(p + 128 + l * 4);

    float mx = fmaxf(fmaxf(fmaxf(v0.x, v0.y), fmaxf(v0.z, v0.w)),
                     fmaxf(fmaxf(v1.x, v1.y), fmaxf(v1.z, v1.w)));
#pragma unroll
    for (int off = 16; off; off >>= 1)
        mx = fmaxf(mx, __shfl_xor_sync(0xFFFFFFFFu, mx, off));

    v0.x = __expf(v0.x - mx); v0.y = __expf(v0.y - mx);
    v0.z = __expf(v0.z - mx); v0.w = __expf(v0.w - mx);
    v1.x = __expf(v1.x - mx); v1.y = __expf(v1.y - mx);
    v1.z = __expf(v1.z - mx); v1.w = __expf(v1.w - mx);

    float sm = v0.x + v0.y + v0.z + v0.w + v1.x + v1.y + v1.z + v1.w;
#pragma unroll
    for (int off = 16; off; off >>= 1)
        sm += __shfl_xor_sync(0xFFFFFFFFu, sm, off);

    const float inv = 1.0f / sm;
    __half2* pp = reinterpret_cast<__half2*>(P + (size_t)row * 256);
    pp[l * 2]          = __floats2half2_rn(v0.x * inv, v0.y * inv);
    pp[l * 2 + 1]      = __floats2half2_rn(v0.z * inv, v0.w * inv);
    pp[64 + l * 2]     = __floats2half2_rn(v1.x * inv, v1.y * inv);
    pp[64 + l * 2 + 1] = __floats2half2_rn(v1.z * inv, v1.w * inv);
}

extern "C" void kernel_launch(void* const* d_in, const int* in_sizes, int n_in,
                              void* d_out, int out_size) {
    (void)in_sizes; (void)n_in; (void)out_size;
    const float* x  = (const float*)d_in[0];
    const float* Wq = (const float*)d_in[1];
    const float* bq = (const float*)d_in[2];
    const float* Wk = (const float*)d_in[3];
    const float* bk = (const float*)d_in[4];
    const float* Wv = (const float*)d_in[5];
    const float* bv = (const float*)d_in[6];
    const float* Wo = (const float*)d_in[7];
    const float* bo = (const float*)d_in[8];
    float* out = (float*)d_out;

    __half *xh, *Qh, *Kh, *VTh, *Ph, *Oh, *WqT, *WkT, *WvT, *WoT;
    float* Sf;
    cudaGetSymbolAddress((void**)&xh,  g_xh);
    cudaGetSymbolAddress((void**)&Qh,  g_Qh);
    cudaGetSymbolAddress((void**)&Kh,  g_Kh);
    cudaGetSymbolAddress((void**)&VTh, g_VTh);
    cudaGetSymbolAddress((void**)&Ph,  g_Ph);
    cudaGetSymbolAddress((void**)&Oh,  g_Oh);
    cudaGetSymbolAddress((void**)&WqT, g_WqT);
    cudaGetSymbolAddress((void**)&WkT, g_WkT);
    cudaGetSymbolAddress((void**)&WvT, g_WvT);
    cudaGetSymbolAddress((void**)&WoT, g_WoT);
    cudaGetSymbolAddress((void**)&Sf,  g_Sf);

    constexpr int AW = BK / 2 + 4;                         // 20 words
    constexpr int SM_A = NST * (128 * AW + 256 * AW) * 4;  // 122880 (128x256)
    constexpr int SM_B = NST * (256 * AW + 128 * AW) * 4;  // 122880 (256x128)
    cudaFuncSetAttribute((const void*)gemm_h<128, 256, 0>,
                         cudaFuncAttributeMaxDynamicSharedMemorySize, SM_A);
    cudaFuncSetAttribute((const void*)gemm_h<128, 256, 1>,
                         cudaFuncAttributeMaxDynamicSharedMemorySize, SM_A);
    cudaFuncSetAttribute((const void*)gemm_h<128, 256, 2>,
                         cudaFuncAttributeMaxDynamicSharedMemorySize, SM_A);
    cudaFuncSetAttribute((const void*)gemm_h<128, 256, 3>,
                         cudaFuncAttributeMaxDynamicSharedMemorySize, SM_A);
    cudaFuncSetAttribute((const void*)gemm_h<256, 128, 4>,
                         cudaFuncAttributeMaxDynamicSharedMemorySize, SM_B);

    const dim3 blk(256);
    const float iscale = 0.088388347648318447f;  // 1/sqrt(128)

    // 0) prepass: convert x, transpose+convert weights
    conv_h<<<16384, blk>>>(x, xh, 16777216);
    transpose_h<<<dim3(64, 64), blk>>>(Wq, WqT, 2048, 2048);
    transpose_h<<<dim3(8, 64), blk>>>(Wk, WkT, 2048, 256);
    transpose_h<<<dim3(8, 64), blk>>>(Wv, WvT, 2048, 256);
    transpose_h<<<dim3(64, 64), blk>>>(Wo, WoT, 2048, 2048);

    // 1) Q = x@Wq + bq -> fp16
    gemm_h<128, 256, 1><<<dim3(8, 64, 1), blk, SM_A>>>(
        xh, WqT, bq, Qh, 2048, 2048, 2048, 2048,
        0, 0, 0, 0, 0, 0, 1, 0, 0, 0, 1, 1, 1.0f);
    // 2) K = x@Wk + bk -> fp16
    gemm_h<128, 256, 1><<<dim3(1, 64, 1), blk, SM_A>>>(
        xh, WkT, bk, Kh, 2048, 2048, 2048, 256,
        0, 0, 0, 0, 0, 0, 1, 0, 0, 0, 1, 1, 1.0f);
    // 3) V = x@Wv + bv, written transposed VT[b][g][d][token] -> fp16
    gemm_h<128, 256, 2><<<dim3(1, 64, 1), blk, SM_A>>>(
        xh, WvT, bv, VTh, 2048, 2048, 2048, 0,
        0, 0, 0, 0, 0, 0, 1, 0, 0, 0, 1, 1, 1.0f);

    // 4) S = scale * Qw @ Kw^T -> fp32 ; z=(b,h,n), 512 batches 256x256 K=128
    gemm_h<128, 256, 3><<<dim3(1, 2, 512), blk, SM_A>>>(
        Qh, Kh, nullptr, Sf, 128, 2048, 256, 256,
        8388608L, 128, 262144L,
        1048576L, 128, 32768L, 2,
        16777216L, 1048576L, 65536L,
        16, 16, iscale);

    // 5) softmax: fp32 S -> fp16 P (fully normalized)
    softmax_h<<<16384, blk>>>(Sf, Ph);

    // 6) O = P @ Vw -> fp16 ; 512 batches 256x128, K=256
    gemm_h<256, 128, 4><<<dim3(1, 1, 512), blk, SM_B>>>(
        Ph, VTh, nullptr, Oh, 256, 256, 4096, 2048,
        16777216L, 1048576L, 65536L,
        1048576L, 524288L, 128L, 2,
        8388608L, 128, 524288L,
        16, 16, 1.0f);

    // 7) out = O @ Wo + bo -> fp32
    gemm_h<128, 256, 0><<<dim3(8, 64, 1), blk, SM_A>>>(
        Oh, WoT, bo, out, 2048, 2048, 2048, 2048,
        0, 0, 0, 0, 0, 0, 1, 0, 0, 0, 1, 1, 1.0f);
}